// round 1
// baseline (speedup 1.0000x reference)
#include <cuda_runtime.h>

// ---------------------------------------------------------------------------
// HierarchicalDownTopFusion — fused, algebraically reduced.
//
//   medium_pooled = mean_m(medium) + (0.25 * sum_m GELU(LN(pool_m@W1+b1))) @ W2 + b2
//   out           = global + MLP2(medium_pooled)
//
// K1: smalls -> pooled -> GEMM1(x4, fused LN/GELU, accumulate) -> GEMM2 -> g_mp
// K2: g_mp -> GEMM1 (LN/GELU) -> GEMM2 -> + global -> out
// Inner GEMMs use packed fp32x2 FMA (fma.rn.f32x2, sm_100+).
// ---------------------------------------------------------------------------

#define BN 65536
#define DD 768
#define HH 256
#define MT 64          // batch rows per CTA
#define KCH 32         // K chunk
#define NT 256         // threads per CTA
#define LN_EPS 1e-5f
#define GS_STRIDE 260  // HH + 4 (bank-conflict pad)
#define XS_STRIDE 33   // KCH + 1

#define SMEM_FLOATS (KCH*HH + MT*GS_STRIDE + MT*XS_STRIDE)
#define SMEM_BYTES  (SMEM_FLOATS * 4)

// scratch for medium_pooled [B, D]  (device global: allocation-guard safe)
__device__ __align__(16) float g_mp[(size_t)BN * DD];

// ---------------- f32x2 helpers ----------------
__device__ __forceinline__ unsigned long long pk2(float x) {
    unsigned long long r; unsigned int u = __float_as_uint(x);
    asm("mov.b64 %0, {%1, %1};" : "=l"(r) : "r"(u));
    return r;
}
__device__ __forceinline__ void fma2(unsigned long long& d,
                                     unsigned long long a, unsigned long long b) {
    asm("fma.rn.f32x2 %0, %1, %2, %0;" : "+l"(d) : "l"(a), "l"(b));
}
__device__ __forceinline__ void upk2(unsigned long long v, float& lo, float& hi) {
    unsigned int a, b;
    asm("mov.b64 {%0, %1}, %2;" : "=r"(a), "=r"(b) : "l"(v));
    lo = __uint_as_float(a); hi = __uint_as_float(b);
}
__device__ __forceinline__ float gelu_exact(float v) {
    return 0.5f * v * (1.0f + erff(v * 0.7071067811865476f));
}

// ---------------- shared building blocks ----------------

// Copy a [KCH][HH] weight block into SMEM (float4, coalesced).
__device__ __forceinline__ void load_w(float* WS, const float* __restrict__ src,
                                       int src_stride, int t) {
#pragma unroll
    for (int i = 0; i < (KCH * HH) / (NT * 4); ++i) {   // 8 iters
        int e4 = i * NT + t;
        int r  = e4 >> 6;
        int c4 = (e4 & 63) << 2;
        *reinterpret_cast<float4*>(WS + r * HH + c4) =
            *reinterpret_cast<const float4*>(src + (size_t)r * src_stride + c4);
    }
}

// One K-chunk of the register-tiled GEMM.
// acc[rr*8+j] packs output cols (32j+2cg, 32j+2cg+1) for row rg*4+rr.
__device__ __forceinline__ void mma_chunk(unsigned long long* acc, const float* WS,
                                          const float* X, int xstride,
                                          int rg, int cg) {
#pragma unroll 4
    for (int k = 0; k < KCH; ++k) {
        unsigned long long wp[8];
        const unsigned long long* wr =
            reinterpret_cast<const unsigned long long*>(WS + k * HH);
#pragma unroll
        for (int j = 0; j < 8; ++j) wp[j] = wr[cg + 16 * j];
#pragma unroll
        for (int rr = 0; rr < 4; ++rr) {
            unsigned long long x2 = pk2(X[(rg * 4 + rr) * xstride + k]);
#pragma unroll
            for (int j = 0; j < 8; ++j) fma2(acc[rr * 8 + j], x2, wp[j]);
        }
    }
}

__device__ __forceinline__ void zero_acc(unsigned long long* acc) {
#pragma unroll
    for (int i = 0; i < 32; ++i) acc[i] = 0ull;
}

// bias + LayerNorm(256) + exact GELU; write (or +=) scale*result into GS.
__device__ __forceinline__ void ln_gelu_epi(const unsigned long long* acc,
                                            const float* __restrict__ bias,
                                            const float* __restrict__ gam,
                                            const float* __restrict__ bet,
                                            float* GS, int rg, int cg,
                                            float scale, bool accumulate) {
#pragma unroll
    for (int rr = 0; rr < 4; ++rr) {
        float h[16];
        float s = 0.f, sq = 0.f;
#pragma unroll
        for (int j = 0; j < 8; ++j) {
            float lo, hi; upk2(acc[rr * 8 + j], lo, hi);
            int c = 32 * j + 2 * cg;
            lo += bias[c]; hi += bias[c + 1];
            h[2 * j] = lo; h[2 * j + 1] = hi;
            s += lo + hi; sq += lo * lo + hi * hi;
        }
        // reduce over the 16 threads (cg 0..15) that share this row
#pragma unroll
        for (int off = 8; off; off >>= 1) {
            s  += __shfl_xor_sync(0xffffffffu, s,  off);
            sq += __shfl_xor_sync(0xffffffffu, sq, off);
        }
        float mu = s * (1.0f / HH);
        float rs = rsqrtf(sq * (1.0f / HH) - mu * mu + LN_EPS);
        int row = rg * 4 + rr;
#pragma unroll
        for (int j = 0; j < 8; ++j) {
            int c = 32 * j + 2 * cg;
            float v0 = (h[2 * j]     - mu) * rs * gam[c]     + bet[c];
            float v1 = (h[2 * j + 1] - mu) * rs * gam[c + 1] + bet[c + 1];
            float g0 = gelu_exact(v0) * scale;
            float g1 = gelu_exact(v1) * scale;
            if (accumulate) {
                GS[row * GS_STRIDE + c]     += g0;
                GS[row * GS_STRIDE + c + 1] += g1;
            } else {
                GS[row * GS_STRIDE + c]     = g0;
                GS[row * GS_STRIDE + c + 1] = g1;
            }
        }
    }
}

// ---------------- Kernel 1: smalls -> medium_pooled (g_mp) ----------------
__global__ __launch_bounds__(NT, 2)
void hdtf_k1(const float* __restrict__ medium, const float* __restrict__ small,
             const float* __restrict__ w1, const float* __restrict__ b1,
             const float* __restrict__ gam, const float* __restrict__ bet,
             const float* __restrict__ w2, const float* __restrict__ b2) {
    extern __shared__ float smem[];
    float* WS = smem;                       // [KCH][HH]
    float* GS = smem + KCH * HH;            // [MT][GS_STRIDE]
    float* XS = GS + MT * GS_STRIDE;        // [MT][XS_STRIDE]

    const int t    = threadIdx.x;
    const int cg   = t & 15;
    const int rg   = t >> 4;
    const int row0 = blockIdx.x * MT;

    // zero the GELU-sum buffer
    for (int i = t; i < MT * GS_STRIDE; i += NT) GS[i] = 0.f;

    const int adj[4][4] = {{0,1,3,4},{1,2,4,5},{3,4,6,7},{4,5,7,8}};

    // -------- Phase A: 4x (pool smalls -> GEMM1 -> LN -> GELU -> += GS) ----
    for (int m = 0; m < 4; ++m) {
        unsigned long long acc[32];
        zero_acc(acc);
        const size_t s0 = (size_t)adj[m][0] * BN * DD;
        const size_t s1 = (size_t)adj[m][1] * BN * DD;
        const size_t s2 = (size_t)adj[m][2] * BN * DD;
        const size_t s3 = (size_t)adj[m][3] * BN * DD;

        for (int kc = 0; kc < DD / KCH; ++kc) {          // 24 chunks
            // pooled X chunk [MT][KCH]
#pragma unroll
            for (int i = 0; i < (MT * KCH) / NT; ++i) {  // 8 iters
                int e = i * NT + t;
                int r = e >> 5, k = e & 31;
                size_t off = (size_t)(row0 + r) * DD + kc * KCH + k;
                float v = small[s0 + off] + small[s1 + off]
                        + small[s2 + off] + small[s3 + off];
                XS[r * XS_STRIDE + k] = 0.25f * v;
            }
            load_w(WS, w1 + (size_t)(kc * KCH) * HH, HH, t);
            __syncthreads();
            mma_chunk(acc, WS, XS, XS_STRIDE, rg, cg);
            __syncthreads();
        }
        ln_gelu_epi(acc, b1, gam, bet, GS, rg, cg, 0.25f, /*accumulate=*/true);
    }
    __syncthreads();

    // -------- Phase B: GS @ W2 + b2 + mean_m(medium) -> g_mp ---------------
    for (int nc = 0; nc < 3; ++nc) {
        unsigned long long acc[32];
        zero_acc(acc);
        for (int kc = 0; kc < HH / KCH; ++kc) {          // 8 chunks
            load_w(WS, w2 + (size_t)(kc * KCH) * DD + nc * HH, DD, t);
            __syncthreads();
            mma_chunk(acc, WS, GS + kc * KCH, GS_STRIDE, rg, cg);
            __syncthreads();
        }
#pragma unroll
        for (int rr = 0; rr < 4; ++rr) {
            int grow = row0 + rg * 4 + rr;
#pragma unroll
            for (int j = 0; j < 8; ++j) {
                int c = nc * HH + 32 * j + 2 * cg;
                float lo, hi; upk2(acc[rr * 8 + j], lo, hi);
                float mx = 0.f, my = 0.f;
#pragma unroll
                for (int m = 0; m < 4; ++m) {
                    float2 mv = *reinterpret_cast<const float2*>(
                        medium + ((size_t)m * BN + grow) * DD + c);
                    mx += mv.x; my += mv.y;
                }
                float2 y;
                y.x = lo + b2[c]     + 0.25f * mx;
                y.y = hi + b2[c + 1] + 0.25f * my;
                *reinterpret_cast<float2*>(&g_mp[(size_t)grow * DD + c]) = y;
            }
        }
    }
}

// ---------------- Kernel 2: g_mp -> MLP2 -> + global -> out ----------------
__global__ __launch_bounds__(NT, 2)
void hdtf_k2(const float* __restrict__ gfeat,
             const float* __restrict__ w1, const float* __restrict__ b1,
             const float* __restrict__ gam, const float* __restrict__ bet,
             const float* __restrict__ w2, const float* __restrict__ b2,
             float* __restrict__ out) {
    extern __shared__ float smem[];
    float* WS = smem;
    float* GS = smem + KCH * HH;
    float* XS = GS + MT * GS_STRIDE;

    const int t    = threadIdx.x;
    const int cg   = t & 15;
    const int rg   = t >> 4;
    const int row0 = blockIdx.x * MT;

    // -------- Phase C: g_mp @ W1 + b1 -> LN -> GELU -> GS ------------------
    {
        unsigned long long acc[32];
        zero_acc(acc);
        for (int kc = 0; kc < DD / KCH; ++kc) {
#pragma unroll
            for (int i = 0; i < (MT * KCH) / NT; ++i) {
                int e = i * NT + t;
                int r = e >> 5, k = e & 31;
                XS[r * XS_STRIDE + k] =
                    g_mp[(size_t)(row0 + r) * DD + kc * KCH + k];
            }
            load_w(WS, w1 + (size_t)(kc * KCH) * HH, HH, t);
            __syncthreads();
            mma_chunk(acc, WS, XS, XS_STRIDE, rg, cg);
            __syncthreads();
        }
        ln_gelu_epi(acc, b1, gam, bet, GS, rg, cg, 1.0f, /*accumulate=*/false);
    }
    __syncthreads();

    // -------- Phase D: GS @ W2 + b2 + global -> out ------------------------
    for (int nc = 0; nc < 3; ++nc) {
        unsigned long long acc[32];
        zero_acc(acc);
        for (int kc = 0; kc < HH / KCH; ++kc) {
            load_w(WS, w2 + (size_t)(kc * KCH) * DD + nc * HH, DD, t);
            __syncthreads();
            mma_chunk(acc, WS, GS + kc * KCH, GS_STRIDE, rg, cg);
            __syncthreads();
        }
#pragma unroll
        for (int rr = 0; rr < 4; ++rr) {
            int grow = row0 + rg * 4 + rr;
#pragma unroll
            for (int j = 0; j < 8; ++j) {
                int c = nc * HH + 32 * j + 2 * cg;
                float lo, hi; upk2(acc[rr * 8 + j], lo, hi);
                float2 gv = *reinterpret_cast<const float2*>(
                    gfeat + (size_t)grow * DD + c);
                float2 y;
                y.x = lo + b2[c]     + gv.x;
                y.y = hi + b2[c + 1] + gv.y;
                *reinterpret_cast<float2*>(&out[(size_t)grow * DD + c]) = y;
            }
        }
    }
}

// ---------------- launch ----------------
extern "C" void kernel_launch(void* const* d_in, const int* in_sizes, int n_in,
                              void* d_out, int out_size) {
    const float* global_feat = (const float*)d_in[0];
    const float* medium      = (const float*)d_in[1];
    const float* small       = (const float*)d_in[2];
    const float* sm_w1 = (const float*)d_in[3];
    const float* sm_b1 = (const float*)d_in[4];
    const float* sm_g  = (const float*)d_in[5];
    const float* sm_be = (const float*)d_in[6];
    const float* sm_w2 = (const float*)d_in[7];
    const float* sm_b2 = (const float*)d_in[8];
    const float* mg_w1 = (const float*)d_in[9];
    const float* mg_b1 = (const float*)d_in[10];
    const float* mg_g  = (const float*)d_in[11];
    const float* mg_be = (const float*)d_in[12];
    const float* mg_w2 = (const float*)d_in[13];
    const float* mg_b2 = (const float*)d_in[14];
    float* out = (float*)d_out;

    cudaFuncSetAttribute(hdtf_k1, cudaFuncAttributeMaxDynamicSharedMemorySize, SMEM_BYTES);
    cudaFuncSetAttribute(hdtf_k2, cudaFuncAttributeMaxDynamicSharedMemorySize, SMEM_BYTES);

    dim3 grid(BN / MT);
    hdtf_k1<<<grid, NT, SMEM_BYTES>>>(medium, small, sm_w1, sm_b1, sm_g, sm_be,
                                      sm_w2, sm_b2);
    hdtf_k2<<<grid, NT, SMEM_BYTES>>>(global_feat, mg_w1, mg_b1, mg_g, mg_be,
                                      mg_w2, mg_b2, out);
}

// round 3
// speedup vs baseline: 1.7159x; 1.7159x over previous
#include <cuda_runtime.h>
#include <cuda_bf16.h>
#include <cstdint>

// ===========================================================================
// HierarchicalDownTopFusion — mma.sync bf16 3-term split (sm_103-safe, no "a"
// features).  Algebra:
//   medium_pooled = mean_m(medium) + (0.25*sum_m GELU(LN(pool_m@W1+b1))) @ W2 + b2
//   out           = global + MLP2(medium_pooled)
// K1 fuses all 4 pools as the M-dim of one 128-row MMA tile (32 batch rows/CTA)
// so each small array is read exactly once from DRAM.
// ===========================================================================

#define BN 65536
#define DD 768
#define HH 256
#define NT 256
#define LN_EPS 1e-5f

// SMEM byte offsets
#define OFF_AHI 0                 // A hi   [128][64] bf16 = 16 KB
#define OFF_ALO 16384             // A lo                    16 KB
#define OFF_BHI 32768             // B hi   [256][64] bf16 = 32 KB
#define OFF_BLO 65536             // B lo                    32 KB
#define OFF_GS  98304             // GS     [128][256] f32 = 128 KB
#define OFF_RED 229376            // RS[256] + RQ[256] f32 =   2 KB
#define SMEM_BYTES 231424         // <= 232448

#define SWZ(o) ((o) ^ (((o) >> 3) & 0x70))

// ---------------- device globals (allocation-guard safe) ----------------
__device__ __align__(16) float g_mp[(size_t)BN * DD];
__device__ __align__(16) __nv_bfloat16 g_w1t_hi[2][HH * DD];
__device__ __align__(16) __nv_bfloat16 g_w1t_lo[2][HH * DD];
__device__ __align__(16) __nv_bfloat16 g_w2t_hi[2][DD * HH];
__device__ __align__(16) __nv_bfloat16 g_w2t_lo[2][DD * HH];

// ---------------- low-level helpers ----------------
__device__ __forceinline__ uint32_t smem_u32(const void* p) {
    uint32_t a;
    asm("{ .reg .u64 t; cvta.to.shared.u64 t, %1; cvt.u32.u64 %0, t; }"
        : "=r"(a) : "l"(p));
    return a;
}
__device__ __forceinline__ void ldsm4(uint32_t* r, uint32_t a) {
    asm volatile("ldmatrix.sync.aligned.m8n8.x4.shared.b16 {%0,%1,%2,%3}, [%4];"
                 : "=r"(r[0]), "=r"(r[1]), "=r"(r[2]), "=r"(r[3]) : "r"(a));
}
__device__ __forceinline__ void mma_bf16(float* c, const uint32_t* a,
                                         const uint32_t* b) {
    asm volatile(
        "mma.sync.aligned.m16n8k16.row.col.f32.bf16.bf16.f32 "
        "{%0,%1,%2,%3}, {%4,%5,%6,%7}, {%8,%9}, {%0,%1,%2,%3};"
        : "+f"(c[0]), "+f"(c[1]), "+f"(c[2]), "+f"(c[3])
        : "r"(a[0]), "r"(a[1]), "r"(a[2]), "r"(a[3]), "r"(b[0]), "r"(b[1]));
}
__device__ __forceinline__ float gelu_exact(float v) {
    return 0.5f * v * (1.0f + erff(v * 0.7071067811865476f));
}

// split a float4 (cols k4..k4+3 of row r) to bf16 hi/lo, SW128-swizzled store
__device__ __forceinline__ void store_A4(char* sm, int r, int k4, float4 v) {
    __nv_bfloat16 h0 = __float2bfloat16(v.x), h1 = __float2bfloat16(v.y);
    __nv_bfloat16 h2 = __float2bfloat16(v.z), h3 = __float2bfloat16(v.w);
    __nv_bfloat16 l0 = __float2bfloat16(v.x - __bfloat162float(h0));
    __nv_bfloat16 l1 = __float2bfloat16(v.y - __bfloat162float(h1));
    __nv_bfloat16 l2 = __float2bfloat16(v.z - __bfloat162float(h2));
    __nv_bfloat16 l3 = __float2bfloat16(v.w - __bfloat162float(h3));
    int off = SWZ(r * 128 + k4 * 2);
    uint2 ph, pl;
    ph.x = ((uint32_t)__bfloat16_as_ushort(h1) << 16) | __bfloat16_as_ushort(h0);
    ph.y = ((uint32_t)__bfloat16_as_ushort(h3) << 16) | __bfloat16_as_ushort(h2);
    pl.x = ((uint32_t)__bfloat16_as_ushort(l1) << 16) | __bfloat16_as_ushort(l0);
    pl.y = ((uint32_t)__bfloat16_as_ushort(l3) << 16) | __bfloat16_as_ushort(l2);
    *reinterpret_cast<uint2*>(sm + OFF_AHI + off) = ph;
    *reinterpret_cast<uint2*>(sm + OFF_ALO + off) = pl;
}

// stage [nrows x 64k] of pre-split weights into B region (swizzled)
template <int NROWS>
__device__ __forceinline__ void stage_B(char* sm,
                                        const __nv_bfloat16* __restrict__ hsrc,
                                        const __nv_bfloat16* __restrict__ lsrc,
                                        int nbase, int stride, int k0, int t) {
#pragma unroll
    for (int i = 0; i < NROWS * 8 / NT; ++i) {
        int e = i * NT + t;
        int n = e >> 3, c16 = e & 7;
        size_t src = (size_t)(nbase + n) * stride + k0 + c16 * 8;
        int dst = SWZ(n * 128 + c16 * 16);
        *reinterpret_cast<int4*>(sm + OFF_BHI + dst) =
            *reinterpret_cast<const int4*>(hsrc + src);
        *reinterpret_cast<int4*>(sm + OFF_BLO + dst) =
            *reinterpret_cast<const int4*>(lsrc + src);
    }
}

// warp-tile 32x128 MMA over one 64-K chunk (3-term split).  acc[32][4].
__device__ __forceinline__ void mma_chunk_128(float (*acc)[4], uint32_t smb,
                                              int mrow0, int n0, int lane) {
    const int aR = (lane & 7) + ((lane >> 3) & 1) * 8;
    const int aK = ((lane >> 4) & 1) * 16;
    const int bR = (lane & 7) + ((lane >> 4) & 1) * 8;
    const int bK = ((lane >> 3) & 1) * 16;
#pragma unroll
    for (int ks = 0; ks < 4; ++ks) {
        uint32_t ah[2][4], al[2][4];
#pragma unroll
        for (int mf = 0; mf < 2; ++mf) {
            int rel = SWZ((mrow0 + mf * 16 + aR) * 128 + ks * 32 + aK);
            ldsm4(ah[mf], smb + OFF_AHI + rel);
            ldsm4(al[mf], smb + OFF_ALO + rel);
        }
#pragma unroll
        for (int nf2 = 0; nf2 < 8; ++nf2) {
            uint32_t bh[4], bl[4];
            int rel = SWZ((n0 + nf2 * 16 + bR) * 128 + ks * 32 + bK);
            ldsm4(bh, smb + OFF_BHI + rel);
            ldsm4(bl, smb + OFF_BLO + rel);
#pragma unroll
            for (int mf = 0; mf < 2; ++mf)
#pragma unroll
                for (int nb = 0; nb < 2; ++nb) {
                    float* c = acc[mf * 16 + nf2 * 2 + nb];
                    mma_bf16(c, ah[mf], bh + nb * 2);
                    mma_bf16(c, ah[mf], bl + nb * 2);
                    mma_bf16(c, al[mf], bh + nb * 2);
                }
        }
    }
}

// warp-tile 32x32 MMA (M rows 0..31) over one 64-K chunk.  acc[8][4].
__device__ __forceinline__ void mma_chunk_32(float (*acc)[4], uint32_t smb,
                                             int n0, int lane) {
    const int aR = (lane & 7) + ((lane >> 3) & 1) * 8;
    const int aK = ((lane >> 4) & 1) * 16;
    const int bR = (lane & 7) + ((lane >> 4) & 1) * 8;
    const int bK = ((lane >> 3) & 1) * 16;
#pragma unroll
    for (int ks = 0; ks < 4; ++ks) {
        uint32_t ah[2][4], al[2][4];
#pragma unroll
        for (int mf = 0; mf < 2; ++mf) {
            int rel = SWZ((mf * 16 + aR) * 128 + ks * 32 + aK);
            ldsm4(ah[mf], smb + OFF_AHI + rel);
            ldsm4(al[mf], smb + OFF_ALO + rel);
        }
#pragma unroll
        for (int nf2 = 0; nf2 < 2; ++nf2) {
            uint32_t bh[4], bl[4];
            int rel = SWZ((n0 + nf2 * 16 + bR) * 128 + ks * 32 + bK);
            ldsm4(bh, smb + OFF_BHI + rel);
            ldsm4(bl, smb + OFF_BLO + rel);
#pragma unroll
            for (int mf = 0; mf < 2; ++mf)
#pragma unroll
                for (int nb = 0; nb < 2; ++nb) {
                    float* c = acc[mf * 4 + nf2 * 2 + nb];
                    mma_bf16(c, ah[mf], bh + nb * 2);
                    mma_bf16(c, ah[mf], bl + nb * 2);
                    mma_bf16(c, al[mf], bh + nb * 2);
                }
        }
    }
}

// bias + LayerNorm(256) + exact GELU -> GS (tile-128 layout). One internal sync.
__device__ __forceinline__ void ln_gelu_store(float (*acc)[4], char* sm,
                                              const float* __restrict__ b1,
                                              const float* __restrict__ gam,
                                              const float* __restrict__ bet,
                                              int wm, int wn, int lane) {
    float* GS = reinterpret_cast<float*>(sm + OFF_GS);
    float* RS = reinterpret_cast<float*>(sm + OFF_RED);
    float* RQ = RS + 256;
    float s[4] = {0, 0, 0, 0}, q[4] = {0, 0, 0, 0};
#pragma unroll
    for (int mf = 0; mf < 2; ++mf)
#pragma unroll
        for (int nf = 0; nf < 16; ++nf) {
            int c = wn * 128 + nf * 8 + 2 * (lane & 3);
            float2 bb = *reinterpret_cast<const float2*>(b1 + c);
            float* a = acc[mf * 16 + nf];
            a[0] += bb.x; a[1] += bb.y; a[2] += bb.x; a[3] += bb.y;
            s[mf * 2]     += a[0] + a[1];
            q[mf * 2]     += a[0] * a[0] + a[1] * a[1];
            s[mf * 2 + 1] += a[2] + a[3];
            q[mf * 2 + 1] += a[2] * a[2] + a[3] * a[3];
        }
#pragma unroll
    for (int h = 0; h < 4; ++h) {
        s[h] += __shfl_xor_sync(0xffffffffu, s[h], 1);
        s[h] += __shfl_xor_sync(0xffffffffu, s[h], 2);
        q[h] += __shfl_xor_sync(0xffffffffu, q[h], 1);
        q[h] += __shfl_xor_sync(0xffffffffu, q[h], 2);
    }
    if ((lane & 3) == 0) {
#pragma unroll
        for (int h = 0; h < 4; ++h) {
            int r = wm * 32 + (lane >> 2) + (h & 1) * 8 + (h >> 1) * 16;
            RS[r * 2 + wn] = s[h];
            RQ[r * 2 + wn] = q[h];
        }
    }
    __syncthreads();
    float mu[4], ri[4];
#pragma unroll
    for (int h = 0; h < 4; ++h) {
        int r = wm * 32 + (lane >> 2) + (h & 1) * 8 + (h >> 1) * 16;
        float ss = RS[r * 2] + RS[r * 2 + 1];
        float qq = RQ[r * 2] + RQ[r * 2 + 1];
        mu[h] = ss * (1.0f / HH);
        ri[h] = rsqrtf(qq * (1.0f / HH) - mu[h] * mu[h] + LN_EPS);
    }
#pragma unroll
    for (int mf = 0; mf < 2; ++mf)
#pragma unroll
        for (int nf = 0; nf < 16; ++nf) {
            int c = wn * 128 + nf * 8 + 2 * (lane & 3);
            float2 gg = *reinterpret_cast<const float2*>(gam + c);
            float2 ee = *reinterpret_cast<const float2*>(bet + c);
            float* a = acc[mf * 16 + nf];
#pragma unroll
            for (int hh = 0; hh < 2; ++hh) {
                int h = mf * 2 + hh;
                int r = wm * 32 + (lane >> 2) + mf * 16 + hh * 8;
                float v0 = (a[hh * 2]     - mu[h]) * ri[h] * gg.x + ee.x;
                float v1 = (a[hh * 2 + 1] - mu[h]) * ri[h] * gg.y + ee.y;
                float2 o; o.x = gelu_exact(v0); o.y = gelu_exact(v1);
                *reinterpret_cast<float2*>(&GS[r * 256 + c]) = o;
            }
        }
}

// ---------------- prep: transpose + bf16-split weights ----------------
__global__ void prep_split(const float* __restrict__ w1s, const float* __restrict__ w2s,
                           const float* __restrict__ w1m, const float* __restrict__ w2m) {
    int idx = blockIdx.x * blockDim.x + threadIdx.x;
    if (idx >= HH * DD) return;
    {
        int n = idx / DD, k = idx % DD;
        float v = w1s[(size_t)k * HH + n];
        __nv_bfloat16 h = __float2bfloat16(v);
        g_w1t_hi[0][idx] = h;
        g_w1t_lo[0][idx] = __float2bfloat16(v - __bfloat162float(h));
        v = w1m[(size_t)k * HH + n];
        h = __float2bfloat16(v);
        g_w1t_hi[1][idx] = h;
        g_w1t_lo[1][idx] = __float2bfloat16(v - __bfloat162float(h));
    }
    {
        int n = idx / HH, k = idx % HH;
        float v = w2s[(size_t)k * DD + n];
        __nv_bfloat16 h = __float2bfloat16(v);
        g_w2t_hi[0][idx] = h;
        g_w2t_lo[0][idx] = __float2bfloat16(v - __bfloat162float(h));
        v = w2m[(size_t)k * DD + n];
        h = __float2bfloat16(v);
        g_w2t_hi[1][idx] = h;
        g_w2t_lo[1][idx] = __float2bfloat16(v - __bfloat162float(h));
    }
}

// ---------------- Kernel 1: 32 batch rows/CTA, 4 pools fused as M=128 -------
__global__ void __launch_bounds__(NT, 1)
hdtf_k1(const float* __restrict__ medium, const float* __restrict__ small,
        const float* __restrict__ b1, const float* __restrict__ gam,
        const float* __restrict__ bet, const float* __restrict__ b2) {
    extern __shared__ char sm[];
    uint32_t smb = smem_u32(sm);
    const int t = threadIdx.x, w = t >> 5, lane = t & 31;
    const int wm = w & 3, wn = w >> 2;
    const int row0 = blockIdx.x * 32;
    float* GS = reinterpret_cast<float*>(sm + OFF_GS);

    // ---- GEMM1: pooled smalls (4 pools stacked in M) @ W1 ----
    float acc[32][4];
#pragma unroll
    for (int i = 0; i < 32; ++i) { acc[i][0]=acc[i][1]=acc[i][2]=acc[i][3]=0.f; }

    const int A0[4] = {0, 1, 3, 4}, A1[4] = {1, 2, 4, 5},
              A2[4] = {3, 4, 6, 7}, A3[4] = {4, 5, 7, 8};

    for (int kc = 0; kc < DD / 64; ++kc) {
#pragma unroll
        for (int p = 0; p < 4; ++p) {
            const float* s0 = small + (size_t)A0[p] * BN * DD;
            const float* s1 = small + (size_t)A1[p] * BN * DD;
            const float* s2 = small + (size_t)A2[p] * BN * DD;
            const float* s3 = small + (size_t)A3[p] * BN * DD;
#pragma unroll
            for (int i = 0; i < 2; ++i) {
                int e = i * NT + t;
                int br = e >> 4, k4 = (e & 15) << 2;
                size_t off = (size_t)(row0 + br) * DD + kc * 64 + k4;
                float4 a = *reinterpret_cast<const float4*>(s0 + off);
                float4 b = *reinterpret_cast<const float4*>(s1 + off);
                float4 c = *reinterpret_cast<const float4*>(s2 + off);
                float4 d = *reinterpret_cast<const float4*>(s3 + off);
                float4 v;
                v.x = 0.25f * (a.x + b.x + c.x + d.x);
                v.y = 0.25f * (a.y + b.y + c.y + d.y);
                v.z = 0.25f * (a.z + b.z + c.z + d.z);
                v.w = 0.25f * (a.w + b.w + c.w + d.w);
                store_A4(sm, p * 32 + br, k4, v);
            }
        }
        stage_B<256>(sm, g_w1t_hi[0], g_w1t_lo[0], 0, DD, kc * 64, t);
        __syncthreads();
        mma_chunk_128(acc, smb, wm * 32, wn * 128, lane);
        __syncthreads();
    }
    ln_gelu_store(acc, sm, b1, gam, bet, wm, wn, lane);
    __syncthreads();

    // ---- pool-mean reduce: GS rows 0..31 <- 0.25 * sum of 4 pool blocks ----
    for (int e = t; e < 32 * 64; e += NT) {
        int r = e >> 6, c4 = (e & 63) << 2;
        float4 x0 = *reinterpret_cast<float4*>(&GS[(r      ) * 256 + c4]);
        float4 x1 = *reinterpret_cast<float4*>(&GS[(r +  32) * 256 + c4]);
        float4 x2 = *reinterpret_cast<float4*>(&GS[(r +  64) * 256 + c4]);
        float4 x3 = *reinterpret_cast<float4*>(&GS[(r +  96) * 256 + c4]);
        float4 y;
        y.x = 0.25f * (x0.x + x1.x + x2.x + x3.x);
        y.y = 0.25f * (x0.y + x1.y + x2.y + x3.y);
        y.z = 0.25f * (x0.z + x1.z + x2.z + x3.z);
        y.w = 0.25f * (x0.w + x1.w + x2.w + x3.w);
        *reinterpret_cast<float4*>(&GS[r * 256 + c4]) = y;
    }
    __syncthreads();

    // ---- GEMM2: GS[32x256] @ W2 + b2 + mean_m(medium) -> g_mp ----
    for (int nt = 0; nt < 3; ++nt) {
        float a2[8][4];
#pragma unroll
        for (int i = 0; i < 8; ++i) { a2[i][0]=a2[i][1]=a2[i][2]=a2[i][3]=0.f; }
        for (int kc = 0; kc < 4; ++kc) {
#pragma unroll
            for (int i = 0; i < 2; ++i) {
                int e = i * NT + t;
                int r = e >> 4, k4 = (e & 15) << 2;
                float4 v = *reinterpret_cast<float4*>(&GS[r * 256 + kc * 64 + k4]);
                store_A4(sm, r, k4, v);
            }
            stage_B<256>(sm, g_w2t_hi[0], g_w2t_lo[0], nt * 256, HH, kc * 64, t);
            __syncthreads();
            mma_chunk_32(a2, smb, w * 32, lane);
            __syncthreads();
        }
#pragma unroll
        for (int mf = 0; mf < 2; ++mf)
#pragma unroll
            for (int nf = 0; nf < 4; ++nf) {
                int c = nt * 256 + w * 32 + nf * 8 + 2 * (lane & 3);
                float2 bb = *reinterpret_cast<const float2*>(b2 + c);
                float* a = a2[mf * 4 + nf];
#pragma unroll
                for (int hh = 0; hh < 2; ++hh) {
                    int r = (lane >> 2) + mf * 16 + hh * 8;
                    int grow = row0 + r;
                    float2 m0 = *reinterpret_cast<const float2*>(medium + ((size_t)0 * BN + grow) * DD + c);
                    float2 m1 = *reinterpret_cast<const float2*>(medium + ((size_t)1 * BN + grow) * DD + c);
                    float2 m2 = *reinterpret_cast<const float2*>(medium + ((size_t)2 * BN + grow) * DD + c);
                    float2 m3 = *reinterpret_cast<const float2*>(medium + ((size_t)3 * BN + grow) * DD + c);
                    float2 o;
                    o.x = a[hh * 2]     + bb.x + 0.25f * (m0.x + m1.x + m2.x + m3.x);
                    o.y = a[hh * 2 + 1] + bb.y + 0.25f * (m0.y + m1.y + m2.y + m3.y);
                    *reinterpret_cast<float2*>(&g_mp[(size_t)grow * DD + c]) = o;
                }
            }
    }
}

// ---------------- Kernel 2: 128 batch rows/CTA, MLP2 + global add ----------
__global__ void __launch_bounds__(NT, 1)
hdtf_k2(const float* __restrict__ gfeat,
        const float* __restrict__ b1, const float* __restrict__ gam,
        const float* __restrict__ bet, const float* __restrict__ b2,
        float* __restrict__ out) {
    extern __shared__ char sm[];
    uint32_t smb = smem_u32(sm);
    const int t = threadIdx.x, w = t >> 5, lane = t & 31;
    const int wm = w & 3, wn = w >> 2;
    const int row0 = blockIdx.x * 128;
    float* GS = reinterpret_cast<float*>(sm + OFF_GS);

    // ---- GEMM1: g_mp[128x768] @ W1 + LN/GELU -> GS ----
    float acc[32][4];
#pragma unroll
    for (int i = 0; i < 32; ++i) { acc[i][0]=acc[i][1]=acc[i][2]=acc[i][3]=0.f; }

    for (int kc = 0; kc < DD / 64; ++kc) {
#pragma unroll
        for (int i = 0; i < 8; ++i) {
            int e = i * NT + t;
            int r = e >> 4, k4 = (e & 15) << 2;
            float4 v = *reinterpret_cast<const float4*>(
                &g_mp[(size_t)(row0 + r) * DD + kc * 64 + k4]);
            store_A4(sm, r, k4, v);
        }
        stage_B<256>(sm, g_w1t_hi[1], g_w1t_lo[1], 0, DD, kc * 64, t);
        __syncthreads();
        mma_chunk_128(acc, smb, wm * 32, wn * 128, lane);
        __syncthreads();
    }
    ln_gelu_store(acc, sm, b1, gam, bet, wm, wn, lane);
    __syncthreads();

    // ---- GEMM2: GS[128x256] @ W2 + b2 + global -> out ----
    for (int nt = 0; nt < 3; ++nt) {
#pragma unroll
        for (int i = 0; i < 32; ++i) { acc[i][0]=acc[i][1]=acc[i][2]=acc[i][3]=0.f; }
        for (int kc = 0; kc < 4; ++kc) {
#pragma unroll
            for (int i = 0; i < 8; ++i) {
                int e = i * NT + t;
                int r = e >> 4, k4 = (e & 15) << 2;
                float4 v = *reinterpret_cast<float4*>(&GS[r * 256 + kc * 64 + k4]);
                store_A4(sm, r, k4, v);
            }
            stage_B<256>(sm, g_w2t_hi[1], g_w2t_lo[1], nt * 256, HH, kc * 64, t);
            __syncthreads();
            mma_chunk_128(acc, smb, wm * 32, wn * 128, lane);
            __syncthreads();
        }
#pragma unroll
        for (int mf = 0; mf < 2; ++mf)
#pragma unroll
            for (int nf = 0; nf < 16; ++nf) {
                int c = nt * 256 + wn * 128 + nf * 8 + 2 * (lane & 3);
                float2 bb = *reinterpret_cast<const float2*>(b2 + c);
                float* a = acc[mf * 16 + nf];
#pragma unroll
                for (int hh = 0; hh < 2; ++hh) {
                    int r = wm * 32 + (lane >> 2) + mf * 16 + hh * 8;
                    int grow = row0 + r;
                    float2 gv = *reinterpret_cast<const float2*>(
                        gfeat + (size_t)grow * DD + c);
                    float2 o;
                    o.x = a[hh * 2]     + bb.x + gv.x;
                    o.y = a[hh * 2 + 1] + bb.y + gv.y;
                    *reinterpret_cast<float2*>(&out[(size_t)grow * DD + c]) = o;
                }
            }
    }
}

// ---------------- launch ----------------
extern "C" void kernel_launch(void* const* d_in, const int* in_sizes, int n_in,
                              void* d_out, int out_size) {
    const float* global_feat = (const float*)d_in[0];
    const float* medium      = (const float*)d_in[1];
    const float* small       = (const float*)d_in[2];
    const float* sm_w1 = (const float*)d_in[3];
    const float* sm_b1 = (const float*)d_in[4];
    const float* sm_g  = (const float*)d_in[5];
    const float* sm_be = (const float*)d_in[6];
    const float* sm_w2 = (const float*)d_in[7];
    const float* sm_b2 = (const float*)d_in[8];
    const float* mg_w1 = (const float*)d_in[9];
    const float* mg_b1 = (const float*)d_in[10];
    const float* mg_g  = (const float*)d_in[11];
    const float* mg_be = (const float*)d_in[12];
    const float* mg_w2 = (const float*)d_in[13];
    const float* mg_b2 = (const float*)d_in[14];
    float* out = (float*)d_out;

    cudaFuncSetAttribute(hdtf_k1, cudaFuncAttributeMaxDynamicSharedMemorySize, SMEM_BYTES);
    cudaFuncSetAttribute(hdtf_k2, cudaFuncAttributeMaxDynamicSharedMemorySize, SMEM_BYTES);

    prep_split<<<(HH * DD + 255) / 256, 256>>>(sm_w1, sm_w2, mg_w1, mg_w2);
    hdtf_k1<<<BN / 32, NT, SMEM_BYTES>>>(medium, small, sm_b1, sm_g, sm_be, sm_b2);
    hdtf_k2<<<BN / 128, NT, SMEM_BYTES>>>(global_feat, mg_b1, mg_g, mg_be, mg_b2, out);
}

// round 4
// speedup vs baseline: 1.9664x; 1.1460x over previous
#include <cuda_runtime.h>
#include <cuda_bf16.h>
#include <cstdint>

// ===========================================================================
// HierarchicalDownTopFusion — mma.sync bf16 3-term split, cp.async pipelined.
//   medium_pooled = mean_m(medium) + (0.25*sum_m GELU(LN(pool_m@W1+b1))) @ W2 + b2
//   out           = global + MLP2(medium_pooled)
// ===========================================================================

#define BN 65536
#define DD 768
#define HH 256
#define NT 256
#define LN_EPS 1e-5f
#define SWZ(o) ((o) ^ (((o) >> 3) & 0x70))

// ---- K1 SMEM layout (bytes) ----
#define K1_A(b)   ((b) * 32768)             // AHI +0 (16K), ALO +16384
#define K1_B(b)   (65536 + (b) * 65536)     // BHI +0 (32K), BLO +32768
#define K1_GS     196608                    // f32 [32][256] = 32K
#define K1_RED    229376                    // RS[256]+RQ[256] = 2K
#define K1_SMEM   231424

// ---- K2 SMEM layout ----
#define K2_A(b)   ((b) * 16384)             // AHI +0 (8K), ALO +8192
#define K2_B(b)   (32768 + (b) * 65536)     // BHI +0 (32K), BLO +32768
#define K2_GSH    163840                    // 4 chunks x [64][128B] = 32K
#define K2_GSL    196608                    // 32K
#define K2_RED    229376                    // 2K
#define K2_SMEM   231424

// ---------------- device globals (allocation-guard safe) ----------------
__device__ __align__(16) __nv_bfloat16 g_mp_hi[(size_t)BN * DD];
__device__ __align__(16) __nv_bfloat16 g_mp_lo[(size_t)BN * DD];
__device__ __align__(16) __nv_bfloat16 g_w1t_hi[2][HH * DD];
__device__ __align__(16) __nv_bfloat16 g_w1t_lo[2][HH * DD];
__device__ __align__(16) __nv_bfloat16 g_w2t_hi[2][DD * HH];
__device__ __align__(16) __nv_bfloat16 g_w2t_lo[2][DD * HH];

// ---------------- low-level helpers ----------------
__device__ __forceinline__ uint32_t smem_u32(const void* p) {
    uint32_t a;
    asm("{ .reg .u64 t; cvta.to.shared.u64 t, %1; cvt.u32.u64 %0, t; }"
        : "=r"(a) : "l"(p));
    return a;
}
#define CP_ASYNC16(dst, src) \
    asm volatile("cp.async.cg.shared.global [%0], [%1], 16;" \
                 :: "r"(dst), "l"(src) : "memory")
#define CP_COMMIT() asm volatile("cp.async.commit_group;" ::: "memory")
#define CP_WAIT0()  asm volatile("cp.async.wait_group 0;" ::: "memory")

__device__ __forceinline__ void ldsm4(uint32_t* r, uint32_t a) {
    asm volatile("ldmatrix.sync.aligned.m8n8.x4.shared.b16 {%0,%1,%2,%3}, [%4];"
                 : "=r"(r[0]), "=r"(r[1]), "=r"(r[2]), "=r"(r[3]) : "r"(a));
}
__device__ __forceinline__ void mma_bf16(float* c, const uint32_t* a,
                                         const uint32_t* b) {
    asm volatile(
        "mma.sync.aligned.m16n8k16.row.col.f32.bf16.bf16.f32 "
        "{%0,%1,%2,%3}, {%4,%5,%6,%7}, {%8,%9}, {%0,%1,%2,%3};"
        : "+f"(c[0]), "+f"(c[1]), "+f"(c[2]), "+f"(c[3])
        : "r"(a[0]), "r"(a[1]), "r"(a[2]), "r"(a[3]), "r"(b[0]), "r"(b[1]));
}
__device__ __forceinline__ float gelu_exact(float v) {
    return 0.5f * v * (1.0f + erff(v * 0.7071067811865476f));
}
__device__ __forceinline__ uint32_t pack_hi(float x, float y) {
    __nv_bfloat16 h0 = __float2bfloat16(x), h1 = __float2bfloat16(y);
    return ((uint32_t)__bfloat16_as_ushort(h1) << 16) | __bfloat16_as_ushort(h0);
}
__device__ __forceinline__ uint32_t pack_lo(float x, float y) {
    __nv_bfloat16 h0 = __float2bfloat16(x), h1 = __float2bfloat16(y);
    __nv_bfloat16 l0 = __float2bfloat16(x - __bfloat162float(h0));
    __nv_bfloat16 l1 = __float2bfloat16(y - __bfloat162float(h1));
    return ((uint32_t)__bfloat16_as_ushort(l1) << 16) | __bfloat16_as_ushort(l0);
}
// split a float4 (cols k4..k4+3 of row r) to bf16 hi/lo planes (swizzled)
__device__ __forceinline__ void store_A4(char* aHi, char* aLo, int r, int k4,
                                         float4 v) {
    int off = SWZ(r * 128 + k4 * 2);
    uint2 ph, pl;
    ph.x = pack_hi(v.x, v.y); ph.y = pack_hi(v.z, v.w);
    pl.x = pack_lo(v.x, v.y); pl.y = pack_lo(v.z, v.w);
    *reinterpret_cast<uint2*>(aHi + off) = ph;
    *reinterpret_cast<uint2*>(aLo + off) = pl;
}

// cp.async stage of 256 weight rows x 64 K (hi+lo planes; BLO = BHI+32768)
__device__ __forceinline__ void cp_stage_B(uint32_t smB,
                                           const __nv_bfloat16* __restrict__ h,
                                           const __nv_bfloat16* __restrict__ l,
                                           int nbase, int stride, int k0, int t) {
#pragma unroll
    for (int i = 0; i < 8; ++i) {
        int e = i * NT + t;
        int n = e >> 3, c = e & 7;
        size_t src = (size_t)(nbase + n) * stride + k0 + c * 8;
        uint32_t dst = smB + SWZ(n * 128 + c * 16);
        CP_ASYNC16(dst, h + src);
        CP_ASYNC16(dst + 32768, l + src);
    }
}

// warp MMA tile: 32 rows x (NF2*16) cols over one 64-K chunk, 3-term split
template <int NF2>
__device__ __forceinline__ void mma_tile(float (*acc)[4], uint32_t aHi,
                                         uint32_t aLo, uint32_t bHi, uint32_t bLo,
                                         int mrow0, int n0, int lane) {
    const int aR = (lane & 7) + ((lane >> 3) & 1) * 8;
    const int aK = ((lane >> 4) & 1) * 16;
    const int bR = (lane & 7) + ((lane >> 4) & 1) * 8;
    const int bK = ((lane >> 3) & 1) * 16;
#pragma unroll
    for (int ks = 0; ks < 4; ++ks) {
        uint32_t ah[2][4], al[2][4];
#pragma unroll
        for (int mf = 0; mf < 2; ++mf) {
            int rel = SWZ((mrow0 + mf * 16 + aR) * 128 + ks * 32 + aK);
            ldsm4(ah[mf], aHi + rel);
            ldsm4(al[mf], aLo + rel);
        }
#pragma unroll
        for (int nf2 = 0; nf2 < NF2; ++nf2) {
            uint32_t bh[4], bl[4];
            int rel = SWZ((n0 + nf2 * 16 + bR) * 128 + ks * 32 + bK);
            ldsm4(bh, bHi + rel);
            ldsm4(bl, bLo + rel);
#pragma unroll
            for (int mf = 0; mf < 2; ++mf)
#pragma unroll
                for (int nb = 0; nb < 2; ++nb) {
                    float* c = acc[(mf * NF2 + nf2) * 2 + nb];
                    mma_bf16(c, ah[mf], bh + nb * 2);
                    mma_bf16(c, ah[mf], bl + nb * 2);
                    mma_bf16(c, al[mf], bh + nb * 2);
                }
        }
    }
}

// ---------------- prep: transpose + bf16-split weights ----------------
__global__ void prep_split(const float* __restrict__ w1s, const float* __restrict__ w2s,
                           const float* __restrict__ w1m, const float* __restrict__ w2m) {
    int idx = blockIdx.x * blockDim.x + threadIdx.x;
    if (idx >= HH * DD) return;
    {
        int n = idx / DD, k = idx % DD;
        float v = w1s[(size_t)k * HH + n];
        __nv_bfloat16 h = __float2bfloat16(v);
        g_w1t_hi[0][idx] = h;
        g_w1t_lo[0][idx] = __float2bfloat16(v - __bfloat162float(h));
        v = w1m[(size_t)k * HH + n];
        h = __float2bfloat16(v);
        g_w1t_hi[1][idx] = h;
        g_w1t_lo[1][idx] = __float2bfloat16(v - __bfloat162float(h));
    }
    {
        int n = idx / HH, k = idx % HH;
        float v = w2s[(size_t)k * DD + n];
        __nv_bfloat16 h = __float2bfloat16(v);
        g_w2t_hi[0][idx] = h;
        g_w2t_lo[0][idx] = __float2bfloat16(v - __bfloat162float(h));
        v = w2m[(size_t)k * DD + n];
        h = __float2bfloat16(v);
        g_w2t_hi[1][idx] = h;
        g_w2t_lo[1][idx] = __float2bfloat16(v - __bfloat162float(h));
    }
}

// ---------------- Kernel 1: 32 batch rows/CTA, 4 pools fused as M=128 -------
__global__ void __launch_bounds__(NT, 1)
hdtf_k1(const float* __restrict__ medium, const float* __restrict__ small,
        const float* __restrict__ b1, const float* __restrict__ gam,
        const float* __restrict__ bet, const float* __restrict__ b2) {
    extern __shared__ char sm[];
    uint32_t smb = smem_u32(sm);
    const int t = threadIdx.x, w = t >> 5, lane = t & 31;
    const int wm = w & 3, wn = w >> 2;
    const int row0 = blockIdx.x * 32;
    float* GS = reinterpret_cast<float*>(sm + K1_GS);
    float* RS = reinterpret_cast<float*>(sm + K1_RED);
    float* RQ = RS + 256;

    const int A0[4] = {0, 1, 3, 4}, A1[4] = {1, 2, 4, 5},
              A2[4] = {3, 4, 6, 7}, A3[4] = {4, 5, 7, 8};

    // zero GS (pool-mean accumulator)
    for (int i = t; i < 32 * 256; i += NT) GS[i] = 0.f;

    // A producer: pool 4 smalls per pool block, split, store into buf
    auto produceA = [&](int kc, int buf) {
        char* aHi = sm + K1_A(buf);
        char* aLo = aHi + 16384;
#pragma unroll
        for (int p = 0; p < 4; ++p) {
            const float* s0 = small + (size_t)A0[p] * BN * DD;
            const float* s1 = small + (size_t)A1[p] * BN * DD;
            const float* s2 = small + (size_t)A2[p] * BN * DD;
            const float* s3 = small + (size_t)A3[p] * BN * DD;
#pragma unroll
            for (int i = 0; i < 2; ++i) {
                int e = i * NT + t;
                int br = e >> 4, k4 = (e & 15) << 2;
                size_t off = (size_t)(row0 + br) * DD + kc * 64 + k4;
                float4 a = *reinterpret_cast<const float4*>(s0 + off);
                float4 b = *reinterpret_cast<const float4*>(s1 + off);
                float4 c = *reinterpret_cast<const float4*>(s2 + off);
                float4 d = *reinterpret_cast<const float4*>(s3 + off);
                float4 v;
                v.x = 0.25f * (a.x + b.x + c.x + d.x);
                v.y = 0.25f * (a.y + b.y + c.y + d.y);
                v.z = 0.25f * (a.z + b.z + c.z + d.z);
                v.w = 0.25f * (a.w + b.w + c.w + d.w);
                store_A4(aHi, aLo, p * 32 + br, k4, v);
            }
        }
    };

    // ---- GEMM1 pipeline: M=128, N=256, K=768 (12 chunks) ----
    float acc[32][4];
#pragma unroll
    for (int i = 0; i < 32; ++i) { acc[i][0]=acc[i][1]=acc[i][2]=acc[i][3]=0.f; }

    produceA(0, 0);
    cp_stage_B(smb + K1_B(0), g_w1t_hi[0], g_w1t_lo[0], 0, DD, 0, t);
    CP_COMMIT();

    for (int kc = 0; kc < 12; ++kc) {
        int cur = kc & 1, nxt = cur ^ 1;
        CP_WAIT0();
        __syncthreads();
        if (kc < 11) {
            cp_stage_B(smb + K1_B(nxt), g_w1t_hi[0], g_w1t_lo[0], 0, DD,
                       (kc + 1) * 64, t);
            CP_COMMIT();
        }
        mma_tile<8>(acc, smb + K1_A(cur), smb + K1_A(cur) + 16384,
                    smb + K1_B(cur), smb + K1_B(cur) + 32768,
                    wm * 32, wn * 128, lane);
        if (kc < 11) produceA(kc + 1, nxt);
    }

    // ---- epilogue: bias + LN(128 rows) + GELU + pool-mean (atomic) ----
    {
        float s[4] = {0, 0, 0, 0}, q[4] = {0, 0, 0, 0};
#pragma unroll
        for (int mf = 0; mf < 2; ++mf)
#pragma unroll
            for (int nf = 0; nf < 16; ++nf) {
                int c = wn * 128 + nf * 8 + 2 * (lane & 3);
                float2 bb = *reinterpret_cast<const float2*>(b1 + c);
                float* a = acc[mf * 16 + nf];
                a[0] += bb.x; a[1] += bb.y; a[2] += bb.x; a[3] += bb.y;
                s[mf * 2]     += a[0] + a[1];
                q[mf * 2]     += a[0] * a[0] + a[1] * a[1];
                s[mf * 2 + 1] += a[2] + a[3];
                q[mf * 2 + 1] += a[2] * a[2] + a[3] * a[3];
            }
#pragma unroll
        for (int h = 0; h < 4; ++h) {
            s[h] += __shfl_xor_sync(0xffffffffu, s[h], 1);
            s[h] += __shfl_xor_sync(0xffffffffu, s[h], 2);
            q[h] += __shfl_xor_sync(0xffffffffu, q[h], 1);
            q[h] += __shfl_xor_sync(0xffffffffu, q[h], 2);
        }
        if ((lane & 3) == 0) {
#pragma unroll
            for (int h = 0; h < 4; ++h) {
                int r = wm * 32 + (lane >> 2) + (h & 1) * 8 + (h >> 1) * 16;
                RS[r * 2 + wn] = s[h];
                RQ[r * 2 + wn] = q[h];
            }
        }
        __syncthreads();
        float mu[4], ri[4];
#pragma unroll
        for (int h = 0; h < 4; ++h) {
            int r = wm * 32 + (lane >> 2) + (h & 1) * 8 + (h >> 1) * 16;
            float ss = RS[r * 2] + RS[r * 2 + 1];
            float qq = RQ[r * 2] + RQ[r * 2 + 1];
            mu[h] = ss * (1.0f / HH);
            ri[h] = rsqrtf(qq * (1.0f / HH) - mu[h] * mu[h] + LN_EPS);
        }
#pragma unroll
        for (int mf = 0; mf < 2; ++mf)
#pragma unroll
            for (int nf = 0; nf < 16; ++nf) {
                int c = wn * 128 + nf * 8 + 2 * (lane & 3);
                float2 gg = *reinterpret_cast<const float2*>(gam + c);
                float2 ee = *reinterpret_cast<const float2*>(bet + c);
                float* a = acc[mf * 16 + nf];
#pragma unroll
                for (int hh = 0; hh < 2; ++hh) {
                    int h = mf * 2 + hh;
                    int rl = (lane >> 2) + mf * 16 + hh * 8;   // 0..31 in pool wm
                    float v0 = (a[hh * 2]     - mu[h]) * ri[h] * gg.x + ee.x;
                    float v1 = (a[hh * 2 + 1] - mu[h]) * ri[h] * gg.y + ee.y;
                    atomicAdd(&GS[rl * 256 + c],     0.25f * gelu_exact(v0));
                    atomicAdd(&GS[rl * 256 + c + 1], 0.25f * gelu_exact(v1));
                }
            }
    }
    __syncthreads();

    // ---- GEMM2 pipeline: GS[32x256] @ W2 (N=768), 12 chunks flattened ----
    auto produceA2 = [&](int cc, int buf) {
        char* aHi = sm + K1_A(buf);
        char* aLo = aHi + 16384;
        int kc = cc & 3;
#pragma unroll
        for (int i = 0; i < 2; ++i) {
            int e = i * NT + t;
            int r = e >> 4, k4 = (e & 15) << 2;
            float4 v = *reinterpret_cast<float4*>(&GS[r * 256 + kc * 64 + k4]);
            store_A4(aHi, aLo, r, k4, v);
        }
    };

    float a2[8][4];
#pragma unroll
    for (int i = 0; i < 8; ++i) { a2[i][0]=a2[i][1]=a2[i][2]=a2[i][3]=0.f; }

    produceA2(0, 0);
    cp_stage_B(smb + K1_B(0), g_w2t_hi[0], g_w2t_lo[0], 0, HH, 0, t);
    CP_COMMIT();

    for (int cc = 0; cc < 12; ++cc) {
        int cur = cc & 1, nxt = cur ^ 1;
        CP_WAIT0();
        __syncthreads();
        if (cc < 11) {
            int c2 = cc + 1;
            cp_stage_B(smb + K1_B(nxt), g_w2t_hi[0], g_w2t_lo[0],
                       (c2 >> 2) * 256, HH, (c2 & 3) * 64, t);
            CP_COMMIT();
        }
        mma_tile<2>(a2, smb + K1_A(cur), smb + K1_A(cur) + 16384,
                    smb + K1_B(cur), smb + K1_B(cur) + 32768,
                    0, w * 32, lane);
        if (cc < 11) produceA2(cc + 1, nxt);

        if ((cc & 3) == 3) {
            int nt = cc >> 2;
#pragma unroll
            for (int mf = 0; mf < 2; ++mf)
#pragma unroll
                for (int nf = 0; nf < 4; ++nf) {
                    int c = nt * 256 + w * 32 + nf * 8 + 2 * (lane & 3);
                    float2 bb = *reinterpret_cast<const float2*>(b2 + c);
                    float* a = a2[mf * 4 + nf];
#pragma unroll
                    for (int hh = 0; hh < 2; ++hh) {
                        int r = (lane >> 2) + mf * 16 + hh * 8;
                        int grow = row0 + r;
                        float2 m0 = *reinterpret_cast<const float2*>(medium + ((size_t)0 * BN + grow) * DD + c);
                        float2 m1 = *reinterpret_cast<const float2*>(medium + ((size_t)1 * BN + grow) * DD + c);
                        float2 m2 = *reinterpret_cast<const float2*>(medium + ((size_t)2 * BN + grow) * DD + c);
                        float2 m3 = *reinterpret_cast<const float2*>(medium + ((size_t)3 * BN + grow) * DD + c);
                        float ox = a[hh * 2]     + bb.x + 0.25f * (m0.x + m1.x + m2.x + m3.x);
                        float oy = a[hh * 2 + 1] + bb.y + 0.25f * (m0.y + m1.y + m2.y + m3.y);
                        size_t gi = ((size_t)grow * DD + c) >> 1;
                        reinterpret_cast<uint32_t*>(g_mp_hi)[gi] = pack_hi(ox, oy);
                        reinterpret_cast<uint32_t*>(g_mp_lo)[gi] = pack_lo(ox, oy);
                    }
                }
#pragma unroll
            for (int i = 0; i < 8; ++i) { a2[i][0]=a2[i][1]=a2[i][2]=a2[i][3]=0.f; }
        }
    }
}

// ---------------- Kernel 2: 64 batch rows/CTA, MLP2 + global add ------------
__global__ void __launch_bounds__(NT, 1)
hdtf_k2(const float* __restrict__ gfeat,
        const float* __restrict__ b1, const float* __restrict__ gam,
        const float* __restrict__ bet, const float* __restrict__ b2,
        float* __restrict__ out) {
    extern __shared__ char sm[];
    uint32_t smb = smem_u32(sm);
    const int t = threadIdx.x, w = t >> 5, lane = t & 31;
    const int wm = w & 1, wn = w >> 1;       // 2 x 4 warp grid (32 x 64 tiles)
    const int row0 = blockIdx.x * 64;
    float* RS = reinterpret_cast<float*>(sm + K2_RED);
    float* RQ = RS + 256;

    // A stage: cp.async g_mp hi/lo planes (64 rows x 64 K)
    auto cpA = [&](int kc, int buf) {
        uint32_t aHi = smb + K2_A(buf);
#pragma unroll
        for (int i = 0; i < 2; ++i) {
            int e = i * NT + t;
            int r = e >> 3, c = e & 7;
            size_t src = (size_t)(row0 + r) * DD + kc * 64 + c * 8;
            uint32_t dst = aHi + SWZ(r * 128 + c * 16);
            CP_ASYNC16(dst, g_mp_hi + src);
            CP_ASYNC16(dst + 8192, g_mp_lo + src);
        }
    };

    // ---- GEMM1 pipeline: M=64, N=256, K=768 ----
    float acc[16][4];
#pragma unroll
    for (int i = 0; i < 16; ++i) { acc[i][0]=acc[i][1]=acc[i][2]=acc[i][3]=0.f; }

    cpA(0, 0);
    cp_stage_B(smb + K2_B(0), g_w1t_hi[1], g_w1t_lo[1], 0, DD, 0, t);
    CP_COMMIT();

    for (int kc = 0; kc < 12; ++kc) {
        int cur = kc & 1, nxt = cur ^ 1;
        CP_WAIT0();
        __syncthreads();
        if (kc < 11) {
            cpA(kc + 1, nxt);
            cp_stage_B(smb + K2_B(nxt), g_w1t_hi[1], g_w1t_lo[1], 0, DD,
                       (kc + 1) * 64, t);
            CP_COMMIT();
        }
        mma_tile<4>(acc, smb + K2_A(cur), smb + K2_A(cur) + 8192,
                    smb + K2_B(cur), smb + K2_B(cur) + 32768,
                    wm * 32, wn * 64, lane);
    }

    // ---- epilogue: bias + LN(64 rows) + GELU -> GS split/swizzled ----
    {
        float s[4] = {0, 0, 0, 0}, q[4] = {0, 0, 0, 0};
#pragma unroll
        for (int mf = 0; mf < 2; ++mf)
#pragma unroll
            for (int nf = 0; nf < 8; ++nf) {
                int c = wn * 64 + nf * 8 + 2 * (lane & 3);
                float2 bb = *reinterpret_cast<const float2*>(b1 + c);
                float* a = acc[mf * 8 + nf];
                a[0] += bb.x; a[1] += bb.y; a[2] += bb.x; a[3] += bb.y;
                s[mf * 2]     += a[0] + a[1];
                q[mf * 2]     += a[0] * a[0] + a[1] * a[1];
                s[mf * 2 + 1] += a[2] + a[3];
                q[mf * 2 + 1] += a[2] * a[2] + a[3] * a[3];
            }
#pragma unroll
        for (int h = 0; h < 4; ++h) {
            s[h] += __shfl_xor_sync(0xffffffffu, s[h], 1);
            s[h] += __shfl_xor_sync(0xffffffffu, s[h], 2);
            q[h] += __shfl_xor_sync(0xffffffffu, q[h], 1);
            q[h] += __shfl_xor_sync(0xffffffffu, q[h], 2);
        }
        if ((lane & 3) == 0) {
#pragma unroll
            for (int h = 0; h < 4; ++h) {
                int r = wm * 32 + (lane >> 2) + (h & 1) * 8 + (h >> 1) * 16;
                RS[r * 4 + wn] = s[h];
                RQ[r * 4 + wn] = q[h];
            }
        }
        __syncthreads();
        float mu[4], ri[4];
#pragma unroll
        for (int h = 0; h < 4; ++h) {
            int r = wm * 32 + (lane >> 2) + (h & 1) * 8 + (h >> 1) * 16;
            float ss = RS[r * 4] + RS[r * 4 + 1] + RS[r * 4 + 2] + RS[r * 4 + 3];
            float qq = RQ[r * 4] + RQ[r * 4 + 1] + RQ[r * 4 + 2] + RQ[r * 4 + 3];
            mu[h] = ss * (1.0f / HH);
            ri[h] = rsqrtf(qq * (1.0f / HH) - mu[h] * mu[h] + LN_EPS);
        }
#pragma unroll
        for (int mf = 0; mf < 2; ++mf)
#pragma unroll
            for (int nf = 0; nf < 8; ++nf) {
                int c = wn * 64 + nf * 8 + 2 * (lane & 3);
                float2 gg = *reinterpret_cast<const float2*>(gam + c);
                float2 ee = *reinterpret_cast<const float2*>(bet + c);
                float* a = acc[mf * 8 + nf];
#pragma unroll
                for (int hh = 0; hh < 2; ++hh) {
                    int h = mf * 2 + hh;
                    int r = wm * 32 + (lane >> 2) + mf * 16 + hh * 8;
                    float v0 = gelu_exact((a[hh * 2]     - mu[h]) * ri[h] * gg.x + ee.x);
                    float v1 = gelu_exact((a[hh * 2 + 1] - mu[h]) * ri[h] * gg.y + ee.y);
                    int chunk = c >> 6;
                    int off = chunk * 8192 + SWZ(r * 128 + (c & 63) * 2);
                    *reinterpret_cast<uint32_t*>(sm + K2_GSH + off) = pack_hi(v0, v1);
                    *reinterpret_cast<uint32_t*>(sm + K2_GSL + off) = pack_lo(v0, v1);
                }
            }
    }
    __syncthreads();

    // ---- GEMM2 pipeline: GS[64x256] @ W2 (N=768); A read in-place from GS ---
#pragma unroll
    for (int i = 0; i < 16; ++i) { acc[i][0]=acc[i][1]=acc[i][2]=acc[i][3]=0.f; }

    cp_stage_B(smb + K2_B(0), g_w2t_hi[1], g_w2t_lo[1], 0, HH, 0, t);
    CP_COMMIT();

    for (int cc = 0; cc < 12; ++cc) {
        int cur = cc & 1, nxt = cur ^ 1;
        CP_WAIT0();
        __syncthreads();
        if (cc < 11) {
            int c2 = cc + 1;
            cp_stage_B(smb + K2_B(nxt), g_w2t_hi[1], g_w2t_lo[1],
                       (c2 >> 2) * 256, HH, (c2 & 3) * 64, t);
            CP_COMMIT();
        }
        int kc = cc & 3;
        mma_tile<4>(acc, smb + K2_GSH + kc * 8192, smb + K2_GSL + kc * 8192,
                    smb + K2_B(cur), smb + K2_B(cur) + 32768,
                    wm * 32, wn * 64, lane);

        if ((cc & 3) == 3) {
            int nt = cc >> 2;
#pragma unroll
            for (int mf = 0; mf < 2; ++mf)
#pragma unroll
                for (int nf = 0; nf < 8; ++nf) {
                    int c = nt * 256 + wn * 64 + nf * 8 + 2 * (lane & 3);
                    float2 bb = *reinterpret_cast<const float2*>(b2 + c);
                    float* a = acc[mf * 8 + nf];
#pragma unroll
                    for (int hh = 0; hh < 2; ++hh) {
                        int r = wm * 32 + (lane >> 2) + mf * 16 + hh * 8;
                        int grow = row0 + r;
                        float2 gv = *reinterpret_cast<const float2*>(
                            gfeat + (size_t)grow * DD + c);
                        float2 o;
                        o.x = a[hh * 2]     + bb.x + gv.x;
                        o.y = a[hh * 2 + 1] + bb.y + gv.y;
                        *reinterpret_cast<float2*>(&out[(size_t)grow * DD + c]) = o;
                    }
                }
#pragma unroll
            for (int i = 0; i < 16; ++i) { acc[i][0]=acc[i][1]=acc[i][2]=acc[i][3]=0.f; }
        }
    }
}

// ---------------- launch ----------------
extern "C" void kernel_launch(void* const* d_in, const int* in_sizes, int n_in,
                              void* d_out, int out_size) {
    const float* global_feat = (const float*)d_in[0];
    const float* medium      = (const float*)d_in[1];
    const float* small       = (const float*)d_in[2];
    const float* sm_w1 = (const float*)d_in[3];
    const float* sm_b1 = (const float*)d_in[4];
    const float* sm_g  = (const float*)d_in[5];
    const float* sm_be = (const float*)d_in[6];
    const float* sm_w2 = (const float*)d_in[7];
    const float* sm_b2 = (const float*)d_in[8];
    const float* mg_w1 = (const float*)d_in[9];
    const float* mg_b1 = (const float*)d_in[10];
    const float* mg_g  = (const float*)d_in[11];
    const float* mg_be = (const float*)d_in[12];
    const float* mg_w2 = (const float*)d_in[13];
    const float* mg_b2 = (const float*)d_in[14];
    float* out = (float*)d_out;

    cudaFuncSetAttribute(hdtf_k1, cudaFuncAttributeMaxDynamicSharedMemorySize, K1_SMEM);
    cudaFuncSetAttribute(hdtf_k2, cudaFuncAttributeMaxDynamicSharedMemorySize, K2_SMEM);

    prep_split<<<(HH * DD + 255) / 256, 256>>>(sm_w1, sm_w2, mg_w1, mg_w2);
    hdtf_k1<<<BN / 32, NT, K1_SMEM>>>(medium, small, sm_b1, sm_g, sm_be, sm_b2);
    hdtf_k2<<<BN / 64, NT, K2_SMEM>>>(global_feat, mg_b1, mg_g, mg_be, mg_b2, out);
}